// round 3
// baseline (speedup 1.0000x reference)
#include <cuda_runtime.h>

#define NN 512
#define DD 512
#define PP 130816

typedef unsigned long long ull;

__device__ float g_ca[NN*DD];
__device__ float g_cb[NN*DD];
__device__ float g_sa[NN*(DD/2)];
__device__ float g_sb[NN*(DD/2)];

__device__ __forceinline__ ull pack2(float lo, float hi) {
    ull r; asm("mov.b64 %0, {%1, %2};" : "=l"(r) : "f"(lo), "f"(hi)); return r;
}
__device__ __forceinline__ void fma2(ull& d, ull a, ull b) {
    asm("fma.rn.f32x2 %0, %1, %2, %0;" : "+l"(d) : "l"(a), "l"(b));
}
__device__ __forceinline__ float2 unpack2(ull v) {
    float2 f; asm("mov.b64 {%0, %1}, %2;" : "=f"(f.x), "=f"(f.y) : "l"(v)); return f;
}

// ---------------------------------------------------------------------------
// Phase 1: C = F(512x512) @ B(512 x Ncols) for 4 weight segments.
// BM=128, BN=32, BK=16, 128 threads, per-thread 8(M)x4(N) with f32x2 M-pairs.
// ---------------------------------------------------------------------------
__global__ __launch_bounds__(128) void proj_gemm(const float* __restrict__ F,
                                                 const float* __restrict__ cw1,
                                                 const float* __restrict__ sw1) {
    __shared__ __align__(16) float As[16 * 132];
    __shared__ __align__(16) float Bs[16 * 32];
    int t = threadIdx.x;
    int cglob = blockIdx.x * 32;
    const float* Bp; float* Cp; int ldb, bcol;
    if (cglob < 512)       { Bp = cw1;             Cp = g_ca; ldb = 512; bcol = cglob; }
    else if (cglob < 1024) { Bp = cw1 + 512 * 512; Cp = g_cb; ldb = 512; bcol = cglob - 512; }
    else if (cglob < 1280) { Bp = sw1;             Cp = g_sa; ldb = 256; bcol = cglob - 1024; }
    else                   { Bp = sw1 + 512 * 256; Cp = g_sb; ldb = 256; bcol = cglob - 1280; }
    int rb = blockIdx.y * 128;
    int rowg = t & 15, colg = t >> 4;

    ull acc[4][4];
#pragma unroll
    for (int a = 0; a < 4; a++)
#pragma unroll
        for (int b = 0; b < 4; b++) acc[a][b] = 0ull;

    for (int k0 = 0; k0 < 512; k0 += 16) {
#pragma unroll
        for (int it = 0; it < 4; it++) {
            int i4 = t + it * 128;
            int row = i4 >> 2, kq = i4 & 3;
            float4 v = *(const float4*)&F[(rb + row) * 512 + k0 + kq * 4];
            As[(kq * 4 + 0) * 132 + row] = v.x;
            As[(kq * 4 + 1) * 132 + row] = v.y;
            As[(kq * 4 + 2) * 132 + row] = v.z;
            As[(kq * 4 + 3) * 132 + row] = v.w;
        }
        {
            int k = t >> 3, cq = t & 7;
            *(float4*)&Bs[k * 32 + cq * 4] = *(const float4*)&Bp[(k0 + k) * ldb + bcol + cq * 4];
        }
        __syncthreads();
#pragma unroll
        for (int k = 0; k < 16; k++) {
            ulonglong2 aA = *(const ulonglong2*)&As[k * 132 + rowg * 8];
            ulonglong2 aB = *(const ulonglong2*)&As[k * 132 + rowg * 8 + 4];
            float4 bv = *(const float4*)&Bs[k * 32 + colg * 4];
            ull am[4] = {aA.x, aA.y, aB.x, aB.y};
            ull bb[4] = {pack2(bv.x, bv.x), pack2(bv.y, bv.y),
                         pack2(bv.z, bv.z), pack2(bv.w, bv.w)};
#pragma unroll
            for (int a = 0; a < 4; a++)
#pragma unroll
                for (int b = 0; b < 4; b++) fma2(acc[a][b], am[a], bb[b]);
        }
        __syncthreads();
    }
#pragma unroll
    for (int mp = 0; mp < 4; mp++) {
        int r = rb + rowg * 8 + mp * 2;
#pragma unroll
        for (int n = 0; n < 4; n++) {
            float2 f = unpack2(acc[mp][n]);
            int c = bcol + colg * 4 + n;
            Cp[r * ldb + c] = f.x;
            Cp[(r + 1) * ldb + c] = f.y;
        }
    }
}

// ---------------------------------------------------------------------------
// Phase 2: pair kernel. Tile = 32 j x 32 i, 8 warps x (4 i per warp, 32 j lanes).
// smem floats: bC 32x516 | bS 32x260 | aC [8w][512k][4s] | aS [8w][256k][4s]
//              | w2 512x12 (pad) | sw2 256
// ---------------------------------------------------------------------------
#define O_BC 0
#define O_BS 16512
#define O_AC 24832
#define O_AS 41216
#define O_W2 49408
#define O_SW 55552
#define SMEMF 55808

__global__ __launch_bounds__(256) void pair_kernel(
    const float* __restrict__ cb1, const float* __restrict__ cw2,
    const float* __restrict__ cb2, const float* __restrict__ sb1,
    const float* __restrict__ sw2, const float* __restrict__ sb2,
    float* __restrict__ out)
{
    extern __shared__ float sm[];
    int jb = blockIdx.x, ib = blockIdx.y;
    if (ib > jb) return;                       // lower-triangle tiles: no i<j pairs
    int jbase = jb * 32, ibase = ib * 32;
    int t = threadIdx.x;

    // stage c_b (coalesced, padded 516/row) and s_b (260/row)
#pragma unroll
    for (int it = 0; it < 16; it++) {
        int i4 = t + it * 256;
        int r = i4 >> 7, q = (i4 & 127) * 4;
        *(float4*)&sm[O_BC + r * 516 + q] = *(const float4*)&g_cb[(jbase + r) * 512 + q];
    }
#pragma unroll
    for (int it = 0; it < 8; it++) {
        int i4 = t + it * 256;
        int r = i4 >> 6, q = (i4 & 63) * 4;
        *(float4*)&sm[O_BS + r * 260 + q] = *(const float4*)&g_sb[(jbase + r) * 256 + q];
    }
    // stage c_a + cb1, slot-interleaved per warp: [w][k][s]
#pragma unroll
    for (int it = 0; it < 16; it++) {
        int i4 = t + it * 256;
        int il = i4 >> 7, q = (i4 & 127) * 4;
        float4 va = *(const float4*)&g_ca[(ibase + il) * 512 + q];
        float4 vb = *(const float4*)&cb1[q];
        float* dst = &sm[O_AC + (il >> 2) * 2048 + q * 4 + (il & 3)];
        dst[0] = va.x + vb.x; dst[4] = va.y + vb.y;
        dst[8] = va.z + vb.z; dst[12] = va.w + vb.w;
    }
    // stage s_a + sb1: [w][k][s]
#pragma unroll
    for (int it = 0; it < 8; it++) {
        int i4 = t + it * 256;
        int il = i4 >> 6, q = (i4 & 63) * 4;
        float4 va = *(const float4*)&g_sa[(ibase + il) * 256 + q];
        float4 vb = *(const float4*)&sb1[q];
        float* dst = &sm[O_AS + (il >> 2) * 1024 + q * 4 + (il & 3)];
        dst[0] = va.x + vb.x; dst[4] = va.y + vb.y;
        dst[8] = va.z + vb.z; dst[12] = va.w + vb.w;
    }
    // cw2 padded to 12 floats/row
    for (int r = t; r < 512; r += 256) {
#pragma unroll
        for (int q = 0; q < 5; q++) {
            float2 v = *(const float2*)&cw2[r * 10 + 2 * q];
            sm[O_W2 + r * 12 + 2 * q] = v.x;
            sm[O_W2 + r * 12 + 2 * q + 1] = v.y;
        }
        sm[O_W2 + r * 12 + 10] = 0.f;
        sm[O_W2 + r * 12 + 11] = 0.f;
    }
    if (t < 64) *(float4*)&sm[O_SW + t * 4] = *(const float4*)&sw2[t * 4];
    __syncthreads();

    int w = t >> 5, lane = t & 31;
    int j = jbase + lane;
    const float* bRow = &sm[O_BC + lane * 516];
    const float* aP   = &sm[O_AC + w * 2048];

    ull cacc[4][5];
#pragma unroll
    for (int s = 0; s < 4; s++)
#pragma unroll
        for (int q = 0; q < 5; q++) cacc[s][q] = 0ull;

    for (int k0 = 0; k0 < 512; k0 += 4) {
        float4 bv = *(const float4*)(bRow + k0);
        float bj4[4] = {bv.x, bv.y, bv.z, bv.w};
#pragma unroll
        for (int kk = 0; kk < 4; kk++) {
            int k = k0 + kk;
            float bj = bj4[kk];
            float4 av = *(const float4*)(aP + k * 4);
            const float* wb = &sm[O_W2 + k * 12];
            ulonglong2 wA = *(const ulonglong2*)wb;
            ulonglong2 wB = *(const ulonglong2*)(wb + 4);
            ull wC = *(const ull*)(wb + 8);
            float hv[4] = {fmaxf(av.x + bj, 0.f), fmaxf(av.y + bj, 0.f),
                           fmaxf(av.z + bj, 0.f), fmaxf(av.w + bj, 0.f)};
#pragma unroll
            for (int s = 0; s < 4; s++) {
                ull hh = pack2(hv[s], hv[s]);
                fma2(cacc[s][0], hh, wA.x); fma2(cacc[s][1], hh, wA.y);
                fma2(cacc[s][2], hh, wB.x); fma2(cacc[s][3], hh, wB.y);
                fma2(cacc[s][4], hh, wC);
            }
        }
    }

    // strength path
    ull sac01 = 0ull, sac23 = 0ull;
    {
        const float* sbRow = &sm[O_BS + lane * 260];
        const float* asP   = &sm[O_AS + w * 1024];
        for (int k0 = 0; k0 < 256; k0 += 4) {
            float4 bv = *(const float4*)(sbRow + k0);
            float4 wv = *(const float4*)&sm[O_SW + k0];
            float bj4[4] = {bv.x, bv.y, bv.z, bv.w};
            float wk4[4] = {wv.x, wv.y, wv.z, wv.w};
#pragma unroll
            for (int kk = 0; kk < 4; kk++) {
                float4 av = *(const float4*)(asP + (k0 + kk) * 4);
                float bj = bj4[kk];
                ull ww = pack2(wk4[kk], wk4[kk]);
                fma2(sac01, pack2(fmaxf(av.x + bj, 0.f), fmaxf(av.y + bj, 0.f)), ww);
                fma2(sac23, pack2(fmaxf(av.z + bj, 0.f), fmaxf(av.w + bj, 0.f)), ww);
            }
        }
    }

    // epilogue
    float2 sv0 = unpack2(sac01), sv1 = unpack2(sac23);
    float sarr[4] = {sv0.x, sv0.y, sv1.x, sv1.y};
    float b2[10];
#pragma unroll
    for (int c = 0; c < 10; c++) b2[c] = __ldg(&cb2[c]);
    float sb = __ldg(&sb2[0]);
#pragma unroll
    for (int s = 0; s < 4; s++) {
        int i = ibase + w * 4 + s;
        if (j <= i) continue;
        float l[10];
#pragma unroll
        for (int q = 0; q < 5; q++) {
            float2 f = unpack2(cacc[s][q]);
            l[2 * q] = f.x + b2[2 * q];
            l[2 * q + 1] = f.y + b2[2 * q + 1];
        }
        float m = l[0]; int idx = 0;
#pragma unroll
        for (int c = 1; c < 10; c++) if (l[c] > m) { m = l[c]; idx = c; }
        float sum = 0.f;
#pragma unroll
        for (int c = 0; c < 10; c++) sum += __expf(l[c] - m);
        float lse = m + __logf(sum);
        int p = i * (1023 - i) / 2 + j - i - 1;
        float2* o2 = (float2*)(out + (size_t)p * 10);
#pragma unroll
        for (int q = 0; q < 5; q++)
            o2[q] = make_float2(l[2 * q] - lse, l[2 * q + 1] - lse);
        out[10 * PP + p] = (float)idx;
        float x = sarr[s] + sb;
        out[11 * PP + p] = 1.f / (1.f + __expf(-x));
    }
}

extern "C" void kernel_launch(void* const* d_in, const int* in_sizes, int n_in,
                              void* d_out, int out_size) {
    (void)in_sizes; (void)n_in; (void)out_size;
    const float* features = (const float*)d_in[0];
    const float* cw1 = (const float*)d_in[1];
    const float* cb1 = (const float*)d_in[2];
    const float* cw2 = (const float*)d_in[3];
    const float* cb2 = (const float*)d_in[4];
    const float* sw1 = (const float*)d_in[5];
    const float* sb1 = (const float*)d_in[6];
    const float* sw2 = (const float*)d_in[7];
    const float* sb2 = (const float*)d_in[8];
    float* out = (float*)d_out;

    cudaFuncSetAttribute(pair_kernel, cudaFuncAttributeMaxDynamicSharedMemorySize,
                         SMEMF * sizeof(float));

    proj_gemm<<<dim3(48, 4), 128>>>(features, cw1, sw1);
    pair_kernel<<<dim3(16, 16), 256, SMEMF * sizeof(float)>>>(
        cb1, cw2, cb2, sb1, sw2, sb2, out);
}

// round 5
// speedup vs baseline: 1.1517x; 1.1517x over previous
#include <cuda_runtime.h>

#define NN 512
#define DD 512
#define PP 130816

typedef unsigned long long ull;

__device__ float g_ca[NN*DD];
__device__ float g_cb[NN*DD];
__device__ float g_sa[NN*(DD/2)];
__device__ float g_sb[NN*(DD/2)];

__device__ __forceinline__ ull pack2(float lo, float hi) {
    ull r; asm("mov.b64 %0, {%1, %2};" : "=l"(r) : "f"(lo), "f"(hi)); return r;
}
__device__ __forceinline__ void fma2(ull& d, ull a, ull b) {
    asm("fma.rn.f32x2 %0, %1, %2, %0;" : "+l"(d) : "l"(a), "l"(b));
}
__device__ __forceinline__ float2 unpack2(ull v) {
    float2 f; asm("mov.b64 {%0, %1}, %2;" : "=f"(f.x), "=f"(f.y) : "l"(v)); return f;
}

// ---------------------------------------------------------------------------
// Phase 1: C = F(512x512) @ B(512 x Ncols), 4 weight segments.
// BM=64, BN=32, BK=16, 128 threads, grid(48,8)=384 blocks.
// B pre-packed as (b,b) f32x2 in smem -> inner loop is pure LDS+FFMA2.
// ---------------------------------------------------------------------------
__global__ __launch_bounds__(128) void proj_gemm(const float* __restrict__ F,
                                                 const float* __restrict__ cw1,
                                                 const float* __restrict__ sw1) {
    __shared__ __align__(16) float As[16 * 68];
    __shared__ __align__(16) ull  Bs[16 * 32];
    int t = threadIdx.x;
    int cglob = blockIdx.x * 32;
    const float* Bp; float* Cp; int ldb, bcol;
    if (cglob < 512)       { Bp = cw1;             Cp = g_ca; ldb = 512; bcol = cglob; }
    else if (cglob < 1024) { Bp = cw1 + 512 * 512; Cp = g_cb; ldb = 512; bcol = cglob - 512; }
    else if (cglob < 1280) { Bp = sw1;             Cp = g_sa; ldb = 256; bcol = cglob - 1024; }
    else                   { Bp = sw1 + 512 * 256; Cp = g_sb; ldb = 256; bcol = cglob - 1280; }
    int rb = blockIdx.y * 64;
    int rowg = t & 15, colg = t >> 4;

    ull acc[2][4];
#pragma unroll
    for (int a = 0; a < 2; a++)
#pragma unroll
        for (int b = 0; b < 4; b++) acc[a][b] = 0ull;

    for (int k0 = 0; k0 < 512; k0 += 16) {
#pragma unroll
        for (int it = 0; it < 2; it++) {
            int i4 = t + it * 128;
            int row = i4 >> 2, kq = i4 & 3;
            float4 v = *(const float4*)&F[(rb + row) * 512 + k0 + kq * 4];
            As[(kq * 4 + 0) * 68 + row] = v.x;
            As[(kq * 4 + 1) * 68 + row] = v.y;
            As[(kq * 4 + 2) * 68 + row] = v.z;
            As[(kq * 4 + 3) * 68 + row] = v.w;
        }
        {
            int k = t >> 3, cq = t & 7;
            float4 v = *(const float4*)&Bp[(k0 + k) * ldb + bcol + cq * 4];
            Bs[k * 32 + cq * 4 + 0] = pack2(v.x, v.x);
            Bs[k * 32 + cq * 4 + 1] = pack2(v.y, v.y);
            Bs[k * 32 + cq * 4 + 2] = pack2(v.z, v.z);
            Bs[k * 32 + cq * 4 + 3] = pack2(v.w, v.w);
        }
        __syncthreads();
#pragma unroll
        for (int k = 0; k < 16; k++) {
            ulonglong2 aA = *(const ulonglong2*)&As[k * 68 + rowg * 4];
            ulonglong2 b0 = *(const ulonglong2*)&Bs[k * 32 + colg * 4];
            ulonglong2 b1 = *(const ulonglong2*)&Bs[k * 32 + colg * 4 + 2];
            fma2(acc[0][0], aA.x, b0.x); fma2(acc[0][1], aA.x, b0.y);
            fma2(acc[0][2], aA.x, b1.x); fma2(acc[0][3], aA.x, b1.y);
            fma2(acc[1][0], aA.y, b0.x); fma2(acc[1][1], aA.y, b0.y);
            fma2(acc[1][2], aA.y, b1.x); fma2(acc[1][3], aA.y, b1.y);
        }
        __syncthreads();
    }
#pragma unroll
    for (int mp = 0; mp < 2; mp++) {
        int r = rb + rowg * 4 + mp * 2;
#pragma unroll
        for (int n = 0; n < 4; n++) {
            float2 f = unpack2(acc[mp][n]);
            int c = bcol + colg * 4 + n;
            Cp[r * ldb + c] = f.x;
            Cp[(r + 1) * ldb + c] = f.y;
        }
    }
}

// ---------------------------------------------------------------------------
// Phase 2: 512 threads = 16 warps; tile 32 j x 32 i; 2 i per warp, 32 j lanes.
// Accumulator lanes are k-parity pairs; cw2 prestaged as (w[2kp],w[2kp+1]) ulls.
// smem floats: bC 32x516 | bS 32x260 | aC [16w][512k][2s] | aS [16w][256k][2s]
//              | w2p ull[256kp][10c] | sw2 256
// ---------------------------------------------------------------------------
#define O_BC 0
#define O_BS 16512
#define O_AC 24832
#define O_AS 41216
#define O_WP 49408
#define O_SW 54528
#define SMEMF 54784

__global__ __launch_bounds__(512) void pair_kernel(
    const float* __restrict__ cb1, const float* __restrict__ cw2,
    const float* __restrict__ cb2, const float* __restrict__ sb1,
    const float* __restrict__ sw2, const float* __restrict__ sb2,
    float* __restrict__ out)
{
    extern __shared__ float sm[];
    int bid = blockIdx.x;
    int jb = (int)((sqrtf(8.0f * bid + 1.0f) - 1.0f) * 0.5f);
    while ((jb + 1) * (jb + 2) / 2 <= bid) jb++;
    while (jb * (jb + 1) / 2 > bid) jb--;
    int ib = bid - jb * (jb + 1) / 2;
    int jbase = jb * 32, ibase = ib * 32;
    int t = threadIdx.x;
    int w = t >> 5, lane = t & 31;

    // stage c_b / s_b (coalesced float4, padded rows)
#pragma unroll
    for (int it = 0; it < 8; it++) {
        int i4 = t + it * 512;
        int r = i4 >> 7, q = (i4 & 127) * 4;
        *(float4*)&sm[O_BC + r * 516 + q] = *(const float4*)&g_cb[(jbase + r) * 512 + q];
    }
#pragma unroll
    for (int it = 0; it < 4; it++) {
        int i4 = t + it * 512;
        int r = i4 >> 6, q = (i4 & 63) * 4;
        *(float4*)&sm[O_BS + r * 260 + q] = *(const float4*)&g_sb[(jbase + r) * 256 + q];
    }
    // stage c_a + cb1: warp w owns rows 2w, 2w+1 -> layout [w][k][2]
#pragma unroll
    for (int kk = 0; kk < 16; kk++) {
        int k = kk * 32 + lane;
        float cv = cb1[k];
        sm[O_AC + w * 1024 + 2 * k + 0] = g_ca[(ibase + 2 * w) * 512 + k] + cv;
        sm[O_AC + w * 1024 + 2 * k + 1] = g_ca[(ibase + 2 * w + 1) * 512 + k] + cv;
    }
    // stage s_a + sb1: [w][k][2]
#pragma unroll
    for (int kk = 0; kk < 8; kk++) {
        int k = kk * 32 + lane;
        float sv = sb1[k];
        sm[O_AS + w * 512 + 2 * k + 0] = g_sa[(ibase + 2 * w) * 256 + k] + sv;
        sm[O_AS + w * 512 + 2 * k + 1] = g_sa[(ibase + 2 * w + 1) * 256 + k] + sv;
    }
    // cw2 k-pair packed: wp[kp*10+c] = (cw2[2kp][c], cw2[2kp+1][c])
    {
        ull* wp = (ull*)&sm[O_WP];
        for (int idx = t; idx < 2560; idx += 512) {
            int kp = idx / 10, c = idx - kp * 10;
            wp[idx] = pack2(cw2[kp * 20 + c], cw2[kp * 20 + 10 + c]);
        }
    }
    if (t < 64) *(float4*)&sm[O_SW + t * 4] = *(const float4*)&sw2[t * 4];
    __syncthreads();

    int j = jbase + lane;
    const float* bRow = &sm[O_BC + lane * 516];
    const float* aP   = &sm[O_AC + w * 1024];
    const ull*   wp   = (const ull*)&sm[O_WP];

    ull acc0[10], acc1[10];
#pragma unroll
    for (int c = 0; c < 10; c++) { acc0[c] = 0ull; acc1[c] = 0ull; }

    for (int k0 = 0; k0 < 512; k0 += 4) {
        float4 bv  = *(const float4*)(bRow + k0);
        float4 a01 = *(const float4*)(aP + 2 * k0);
        float4 a23 = *(const float4*)(aP + 2 * k0 + 4);
        float h00 = fmaxf(a01.x + bv.x, 0.f), h01 = fmaxf(a01.y + bv.x, 0.f);
        float h10 = fmaxf(a01.z + bv.y, 0.f), h11 = fmaxf(a01.w + bv.y, 0.f);
        float h20 = fmaxf(a23.x + bv.z, 0.f), h21 = fmaxf(a23.y + bv.z, 0.f);
        float h30 = fmaxf(a23.z + bv.w, 0.f), h31 = fmaxf(a23.w + bv.w, 0.f);
        ull hp0s0 = pack2(h00, h10), hp0s1 = pack2(h01, h11);
        ull hp1s0 = pack2(h20, h30), hp1s1 = pack2(h21, h31);
        const ull* w0 = wp + (k0 >> 1) * 10;
#pragma unroll
        for (int c = 0; c < 10; c++) {
            ull wc0 = w0[c], wc1 = w0[10 + c];
            fma2(acc0[c], hp0s0, wc0); fma2(acc1[c], hp0s1, wc0);
            fma2(acc0[c], hp1s0, wc1); fma2(acc1[c], hp1s1, wc1);
        }
    }

    // strength path (k-pair lanes as well; sw2 read directly as ull pairs)
    ull sacc0 = 0ull, sacc1 = 0ull;
    {
        const float* sbRow = &sm[O_BS + lane * 260];
        const float* sP    = &sm[O_AS + w * 512];
        const float* swp   = &sm[O_SW];
        for (int k0 = 0; k0 < 256; k0 += 4) {
            float4 bv  = *(const float4*)(sbRow + k0);
            float4 a01 = *(const float4*)(sP + 2 * k0);
            float4 a23 = *(const float4*)(sP + 2 * k0 + 4);
            ull ww01 = *(const ull*)(swp + k0);
            ull ww23 = *(const ull*)(swp + k0 + 2);
            float h00 = fmaxf(a01.x + bv.x, 0.f), h01 = fmaxf(a01.y + bv.x, 0.f);
            float h10 = fmaxf(a01.z + bv.y, 0.f), h11 = fmaxf(a01.w + bv.y, 0.f);
            float h20 = fmaxf(a23.x + bv.z, 0.f), h21 = fmaxf(a23.y + bv.z, 0.f);
            float h30 = fmaxf(a23.z + bv.w, 0.f), h31 = fmaxf(a23.w + bv.w, 0.f);
            fma2(sacc0, pack2(h00, h10), ww01); fma2(sacc1, pack2(h01, h11), ww01);
            fma2(sacc0, pack2(h20, h30), ww23); fma2(sacc1, pack2(h21, h31), ww23);
        }
    }

    // epilogue
    float2 fs0 = unpack2(sacc0), fs1 = unpack2(sacc1);
    float svv[2] = {fs0.x + fs0.y, fs1.x + fs1.y};
    float b2[10];
#pragma unroll
    for (int c = 0; c < 10; c++) b2[c] = __ldg(&cb2[c]);
    float sbv = __ldg(&sb2[0]);
#pragma unroll
    for (int s = 0; s < 2; s++) {
        int i = ibase + w * 2 + s;
        if (j <= i) continue;
        float l[10];
#pragma unroll
        for (int c = 0; c < 10; c++) {
            float2 f = unpack2(s ? acc1[c] : acc0[c]);
            l[c] = f.x + f.y + b2[c];
        }
        float m = l[0]; int idx = 0;
#pragma unroll
        for (int c = 1; c < 10; c++) if (l[c] > m) { m = l[c]; idx = c; }
        float sum = 0.f;
#pragma unroll
        for (int c = 0; c < 10; c++) sum += __expf(l[c] - m);
        float lse = m + __logf(sum);
        int p = i * (1023 - i) / 2 + j - i - 1;
        float2* o2 = (float2*)(out + (size_t)p * 10);
#pragma unroll
        for (int q = 0; q < 5; q++)
            o2[q] = make_float2(l[2 * q] - lse, l[2 * q + 1] - lse);
        out[10 * PP + p] = (float)idx;
        float x = svv[s] + sbv;
        out[11 * PP + p] = 1.f / (1.f + __expf(-x));
    }
}

extern "C" void kernel_launch(void* const* d_in, const int* in_sizes, int n_in,
                              void* d_out, int out_size) {
    (void)in_sizes; (void)n_in; (void)out_size;
    const float* features = (const float*)d_in[0];
    const float* cw1 = (const float*)d_in[1];
    const float* cb1 = (const float*)d_in[2];
    const float* cw2 = (const float*)d_in[3];
    const float* cb2 = (const float*)d_in[4];
    const float* sw1 = (const float*)d_in[5];
    const float* sb1 = (const float*)d_in[6];
    const float* sw2 = (const float*)d_in[7];
    const float* sb2 = (const float*)d_in[8];
    float* out = (float*)d_out;

    cudaFuncSetAttribute(pair_kernel, cudaFuncAttributeMaxDynamicSharedMemorySize,
                         SMEMF * sizeof(float));

    proj_gemm<<<dim3(48, 8), 128>>>(features, cw1, sw1);
    pair_kernel<<<136, 512, SMEMF * sizeof(float)>>>(
        cb1, cw2, cb2, sb1, sw2, sb2, out);
}